// round 14
// baseline (speedup 1.0000x reference)
#include <cuda_runtime.h>
#include <cuda_bf16.h>
#include <cuda_fp16.h>
#include <cstdint>

#define D 128
#define OUTD 128
#define MAXN 100000
#define EPS 0.1f
#define CAP 48        // per-dst bucket capacity (avg in-degree 6.4)
#define OVFCAP 262144 // overflow list capacity (correctness fallback)

// Scratch (allocation-free rule: __device__ globals)
__device__ __half  g_x_h[(size_t)MAXN * D];
__device__ float   g_alpha_l[MAXN];
__device__ float   g_alpha_r[MAXN];
__device__ int     g_is64;
__device__ uint32_t g_W_hi[128 * 64];   // bf16x2 packed, [n][k/2]
__device__ uint32_t g_W_lo[128 * 64];
__device__ int     g_cnt[MAXN];
__device__ uint2   g_bucket[(size_t)MAXN * CAP];  // (src, coeff bits)
__device__ int     g_ovf_cnt;
__device__ uint4   g_ovf[OVFCAP];                 // (dst, src, coeff bits, 0)

// ---------------------------------------------------------------------------
// Kernel 1: fused alpha + prep.
// blocks [0, ablocks): alpha logits + fp16 copy of x (warp per node)
// blocks [ablocks, ablocks+32): W -> bf16 hi/lo
// blocks [.., ..+nzero): zero cnt
// last block: int64/int32 detect + zero overflow counter
// ---------------------------------------------------------------------------
__global__ void alpha_prep_kernel(const float* __restrict__ x,
                                  const float* __restrict__ att_l,
                                  const float* __restrict__ att_r,
                                  const float* __restrict__ W,
                                  const unsigned int* __restrict__ ei_words,
                                  int N, int E, int ablocks, int nzero) {
    int b = blockIdx.x;
    if (b < ablocks) {
        int warp = b * 8 + ((int)threadIdx.x >> 5);
        int lane = threadIdx.x & 31;
        if (warp >= N) return;

        float4 xv = reinterpret_cast<const float4*>(x + (size_t)warp * D)[lane];
        float4 al = reinterpret_cast<const float4*>(att_l)[lane];
        float4 ar = reinterpret_cast<const float4*>(att_r)[lane];

        float sl = xv.x * al.x + xv.y * al.y + xv.z * al.z + xv.w * al.w;
        float sr = xv.x * ar.x + xv.y * ar.y + xv.z * ar.z + xv.w * ar.w;
#pragma unroll
        for (int o = 16; o > 0; o >>= 1) {
            sl += __shfl_xor_sync(0xffffffffu, sl, o);
            sr += __shfl_xor_sync(0xffffffffu, sr, o);
        }
        if (lane == 0) {
            g_alpha_l[warp] = sl;
            g_alpha_r[warp] = sr;
        }

        __half2 h01 = __floats2half2_rn(xv.x, xv.y);
        __half2 h23 = __floats2half2_rn(xv.z, xv.w);
        uint2 hw = make_uint2(*reinterpret_cast<uint32_t*>(&h01),
                              *reinterpret_cast<uint32_t*>(&h23));
        reinterpret_cast<uint2*>(g_x_h + (size_t)warp * D)[lane] = hw;
    } else if (b < ablocks + 32) {
        int idx = (b - ablocks) * 256 + threadIdx.x;  // < 8192
        int n = idx >> 6, k2 = idx & 63;
        float w0 = W[n * D + 2 * k2];
        float w1 = W[n * D + 2 * k2 + 1];
        __nv_bfloat16 h0 = __float2bfloat16_rn(w0);
        __nv_bfloat16 h1 = __float2bfloat16_rn(w1);
        float l0 = w0 - __bfloat162float(h0);
        float l1 = w1 - __bfloat162float(h1);
        __nv_bfloat162 hp = __halves2bfloat162(h0, h1);
        __nv_bfloat162 lp = __halves2bfloat162(__float2bfloat16_rn(l0),
                                               __float2bfloat16_rn(l1));
        g_W_hi[idx] = *reinterpret_cast<uint32_t*>(&hp);
        g_W_lo[idx] = *reinterpret_cast<uint32_t*>(&lp);
    } else if (b < ablocks + 32 + nzero) {
        int i = (b - ablocks - 32) * 256 + threadIdx.x;
        if (i < N) g_cnt[i] = 0;
    } else {
        __shared__ int bad;
        if (threadIdx.x == 0) { bad = 0; g_ovf_cnt = 0; }
        __syncthreads();
        int nchk = E < 1024 ? E : 1024;
        for (int k = threadIdx.x; k < nchk; k += blockDim.x)
            if (ei_words[2 * k + 1] != 0u) bad = 1;
        __syncthreads();
        if (threadIdx.x == 0) g_is64 = bad ? 0 : 1;
    }
}

// ---------------------------------------------------------------------------
// Kernel 2: fill per-dst buckets with (src, coeff). Thread per edge.
// ---------------------------------------------------------------------------
__global__ void fill_kernel(const void* __restrict__ ei_raw,
                            const float* __restrict__ ew,
                            int E) {
    int e = blockIdx.x * blockDim.x + threadIdx.x;
    if (e >= E) return;

    int src, dst;
    if (g_is64) {
        const long long* ei = (const long long*)ei_raw;
        src = (int)ei[e];
        dst = (int)ei[(size_t)E + e];
    } else {
        const int* ei = (const int*)ei_raw;
        src = ei[e];
        dst = ei[(size_t)E + e];
    }
    float c = tanhf(g_alpha_l[src] + g_alpha_r[dst]) * ew[e];

    int slot = atomicAdd(&g_cnt[dst], 1);
    if (slot < CAP) {
        g_bucket[(size_t)dst * CAP + slot] = make_uint2((unsigned)src, __float_as_uint(c));
    } else {
        int o = atomicAdd(&g_ovf_cnt, 1);
        if (o < OVFCAP)
            g_ovf[o] = make_uint4((unsigned)dst, (unsigned)src, __float_as_uint(c), 0u);
    }
}

// ---------------------------------------------------------------------------
// Kernel 3: FUSED pull + GEMM. Persistent, 256 threads, 2 CTAs/SM.
// Per 64-row tile: each warp pulls 8 nodes (8-deep MLP bucket loop, fp16
// gathers, relu(EPS*x0+sum)), converts to bf16 hi/lo, writes DIRECTLY into
// the A smem tile. Then bf16x3 mma.m16n8k16 and fp32 epilogue.
// g_agg round-trip (102 MB DRAM) eliminated.
// ---------------------------------------------------------------------------
#define PITCH 68   // words per row (64 + 4 pad)

#define SM_WHI 0
#define SM_WLO (128 * PITCH)
#define SM_AHI (2 * 128 * PITCH)
#define SM_ALO (2 * 128 * PITCH + 64 * PITCH)
#define SM_WORDS (2 * 128 * PITCH + 2 * 64 * PITCH)

__device__ __forceinline__ void mma_bf16(float* d, const uint32_t* a, const uint32_t* b) {
    asm volatile(
        "mma.sync.aligned.m16n8k16.row.col.f32.bf16.bf16.f32 "
        "{%0,%1,%2,%3}, {%4,%5,%6,%7}, {%8,%9}, {%0,%1,%2,%3};"
        : "+f"(d[0]), "+f"(d[1]), "+f"(d[2]), "+f"(d[3])
        : "r"(a[0]), "r"(a[1]), "r"(a[2]), "r"(a[3]), "r"(b[0]), "r"(b[1]));
}

__global__ __launch_bounds__(256, 2)
void pullgemm_kernel(const float* __restrict__ x0,
                     const float* __restrict__ bias,
                     float* __restrict__ out,
                     int N) {
    extern __shared__ uint32_t sm[];
    int tid = threadIdx.x;
    int lane = tid & 31;
    int wid = tid >> 5;
    int warpM = wid >> 2;
    int warpN = wid & 3;

    // ---- load packed W hi/lo into smem once ----
    for (int i = tid; i < 128 * 16; i += 256) {
        int r = i >> 4;
        int c4 = i & 15;
        uint4 h = reinterpret_cast<const uint4*>(g_W_hi)[(size_t)r * 16 + c4];
        uint4 l = reinterpret_cast<const uint4*>(g_W_lo)[(size_t)r * 16 + c4];
        *reinterpret_cast<uint4*>(&sm[SM_WHI + r * PITCH + c4 * 4]) = h;
        *reinterpret_cast<uint4*>(&sm[SM_WLO + r * PITCH + c4 * 4]) = l;
    }

    float bv[4][2];
#pragma unroll
    for (int nt = 0; nt < 4; nt++) {
        int col = warpN * 32 + nt * 8 + (lane & 3) * 2;
        bv[nt][0] = bias[col];
        bv[nt][1] = bias[col + 1];
    }
    __syncthreads();

    int ntiles = (N + 63) >> 6;
    for (int t = blockIdx.x; t < ntiles; t += gridDim.x) {
        int m0 = t << 6;

        // ================= pull phase: warp pulls rows wid*8 .. wid*8+7 ====
        for (int rr = 0; rr < 8; rr++) {
            int r = wid * 8 + rr;
            int node = m0 + r;
            uint2 hwv = make_uint2(0u, 0u), lwv = make_uint2(0u, 0u);
            if (node < N) {
                float4 x0v = reinterpret_cast<const float4*>(x0 + (size_t)node * D)[lane];

                int cntr = g_cnt[node];
                int cnt = cntr > CAP ? CAP : cntr;

                const uint2* b = g_bucket + (size_t)node * CAP;
                float ax = 0.f, ay = 0.f, az = 0.f, aw = 0.f;

                for (int j0 = 0; j0 < cnt; j0 += 8) {
                    uint2 pe[8];
                    uint2 hw[8];
#pragma unroll
                    for (int i = 0; i < 8; i++) {
                        int jc = j0 + i;
                        if (jc > cnt - 1) jc = cnt - 1;   // valid: cnt >= 1 here
                        pe[i] = b[jc];
                        if (j0 + i >= cnt) pe[i].y = 0u;
                    }
#pragma unroll
                    for (int i = 0; i < 8; i++)
                        hw[i] = reinterpret_cast<const uint2*>(
                                    g_x_h + (size_t)pe[i].x * D)[lane];
#pragma unroll
                    for (int i = 0; i < 8; i++) {
                        float c = __uint_as_float(pe[i].y);
                        float2 f01 = __half22float2(*reinterpret_cast<__half2*>(&hw[i].x));
                        float2 f23 = __half22float2(*reinterpret_cast<__half2*>(&hw[i].y));
                        ax = fmaf(c, f01.x, ax);
                        ay = fmaf(c, f01.y, ay);
                        az = fmaf(c, f23.x, az);
                        aw = fmaf(c, f23.y, aw);
                    }
                }

                if (cntr > CAP) {  // essentially-never overflow scan
                    int novf = g_ovf_cnt;
                    if (novf > OVFCAP) novf = OVFCAP;
                    for (int k = 0; k < novf; k++) {
                        uint4 e = g_ovf[k];
                        if (e.x == (unsigned)node) {
                            float c = __uint_as_float(e.z);
                            uint2 hw = reinterpret_cast<const uint2*>(
                                           g_x_h + (size_t)e.y * D)[lane];
                            float2 f01 = __half22float2(*reinterpret_cast<__half2*>(&hw.x));
                            float2 f23 = __half22float2(*reinterpret_cast<__half2*>(&hw.y));
                            ax = fmaf(c, f01.x, ax);
                            ay = fmaf(c, f01.y, ay);
                            az = fmaf(c, f23.x, az);
                            aw = fmaf(c, f23.y, aw);
                        }
                    }
                }

                float o0 = fmaxf(fmaf(EPS, x0v.x, ax), 0.f);
                float o1 = fmaxf(fmaf(EPS, x0v.y, ay), 0.f);
                float o2 = fmaxf(fmaf(EPS, x0v.z, az), 0.f);
                float o3 = fmaxf(fmaf(EPS, x0v.w, aw), 0.f);

                __nv_bfloat16 h0 = __float2bfloat16_rn(o0);
                __nv_bfloat16 h1 = __float2bfloat16_rn(o1);
                __nv_bfloat16 h2 = __float2bfloat16_rn(o2);
                __nv_bfloat16 h3 = __float2bfloat16_rn(o3);
                __nv_bfloat162 hp0 = __halves2bfloat162(h0, h1);
                __nv_bfloat162 hp1 = __halves2bfloat162(h2, h3);
                __nv_bfloat162 lp0 = __halves2bfloat162(
                    __float2bfloat16_rn(o0 - __bfloat162float(h0)),
                    __float2bfloat16_rn(o1 - __bfloat162float(h1)));
                __nv_bfloat162 lp1 = __halves2bfloat162(
                    __float2bfloat16_rn(o2 - __bfloat162float(h2)),
                    __float2bfloat16_rn(o3 - __bfloat162float(h3)));
                hwv = make_uint2(*reinterpret_cast<uint32_t*>(&hp0),
                                 *reinterpret_cast<uint32_t*>(&hp1));
                lwv = make_uint2(*reinterpret_cast<uint32_t*>(&lp0),
                                 *reinterpret_cast<uint32_t*>(&lp1));
            }
            // word c = lane*2 covers features 4*lane .. 4*lane+3
            *reinterpret_cast<uint2*>(&sm[SM_AHI + r * PITCH + lane * 2]) = hwv;
            *reinterpret_cast<uint2*>(&sm[SM_ALO + r * PITCH + lane * 2]) = lwv;
        }
        __syncthreads();

        // ================= mma phase ========================================
        float acc[2][4][4];
#pragma unroll
        for (int mt = 0; mt < 2; mt++)
#pragma unroll
            for (int nt = 0; nt < 4; nt++)
#pragma unroll
                for (int i = 0; i < 4; i++) acc[mt][nt][i] = 0.f;

#pragma unroll
        for (int ks = 0; ks < 8; ks++) {
            int w0 = ks * 8 + (lane & 3);
            uint32_t ahi[2][4], alo[2][4];
#pragma unroll
            for (int mt = 0; mt < 2; mt++) {
                int r = warpM * 32 + mt * 16 + (lane >> 2);
                ahi[mt][0] = sm[SM_AHI + r * PITCH + w0];
                ahi[mt][1] = sm[SM_AHI + (r + 8) * PITCH + w0];
                ahi[mt][2] = sm[SM_AHI + r * PITCH + w0 + 4];
                ahi[mt][3] = sm[SM_AHI + (r + 8) * PITCH + w0 + 4];
                alo[mt][0] = sm[SM_ALO + r * PITCH + w0];
                alo[mt][1] = sm[SM_ALO + (r + 8) * PITCH + w0];
                alo[mt][2] = sm[SM_ALO + r * PITCH + w0 + 4];
                alo[mt][3] = sm[SM_ALO + (r + 8) * PITCH + w0 + 4];
            }
            uint32_t bhi[4][2], blo[4][2];
#pragma unroll
            for (int nt = 0; nt < 4; nt++) {
                int n = warpN * 32 + nt * 8 + (lane >> 2);
                bhi[nt][0] = sm[SM_WHI + n * PITCH + w0];
                bhi[nt][1] = sm[SM_WHI + n * PITCH + w0 + 4];
                blo[nt][0] = sm[SM_WLO + n * PITCH + w0];
                blo[nt][1] = sm[SM_WLO + n * PITCH + w0 + 4];
            }
#pragma unroll
            for (int mt = 0; mt < 2; mt++)
#pragma unroll
                for (int nt = 0; nt < 4; nt++) {
                    mma_bf16(acc[mt][nt], ahi[mt], blo[nt]);
                    mma_bf16(acc[mt][nt], alo[mt], bhi[nt]);
                    mma_bf16(acc[mt][nt], ahi[mt], bhi[nt]);
                }
        }

        // ================= epilogue ========================================
#pragma unroll
        for (int mt = 0; mt < 2; mt++) {
            int r0 = m0 + warpM * 32 + mt * 16 + (lane >> 2);
#pragma unroll
            for (int nt = 0; nt < 4; nt++) {
                int col = warpN * 32 + nt * 8 + (lane & 3) * 2;
                if (r0 < N) {
                    float2 v = make_float2(acc[mt][nt][0] + bv[nt][0],
                                           acc[mt][nt][1] + bv[nt][1]);
                    *reinterpret_cast<float2*>(out + (size_t)r0 * OUTD + col) = v;
                }
                if (r0 + 8 < N) {
                    float2 v = make_float2(acc[mt][nt][2] + bv[nt][0],
                                           acc[mt][nt][3] + bv[nt][1]);
                    *reinterpret_cast<float2*>(out + (size_t)(r0 + 8) * OUTD + col) = v;
                }
            }
        }
        __syncthreads();  // protect A smem before next tile's pull
    }
}

// ---------------------------------------------------------------------------
// Launch: 3 kernels. alpha+prep -> fill -> fused pull-gemm.
// ---------------------------------------------------------------------------
extern "C" void kernel_launch(void* const* d_in, const int* in_sizes, int n_in,
                              void* d_out, int out_size) {
    const float* x      = (const float*)d_in[0];
    const float* x0     = (const float*)d_in[1];
    const float* ew     = (const float*)d_in[2];
    const float* att_l  = (const float*)d_in[3];
    const float* att_r  = (const float*)d_in[4];
    const float* W      = (const float*)d_in[5];
    const float* bias   = (const float*)d_in[6];
    const void*  ei     = (const void*)d_in[7];
    float* out = (float*)d_out;

    int N = in_sizes[1] / D;
    int E = in_sizes[2];

    static bool attr_set = false;
    if (!attr_set) {
        cudaFuncSetAttribute(pullgemm_kernel,
                             cudaFuncAttributeMaxDynamicSharedMemorySize,
                             SM_WORDS * 4);
        attr_set = true;
    }

    int ablocks = (N + 7) / 8;
    int nzero = (N + 255) / 256;
    alpha_prep_kernel<<<ablocks + 32 + nzero + 1, 256>>>(
        x, att_l, att_r, W, (const unsigned int*)ei, N, E, ablocks, nzero);

    fill_kernel<<<(E + 255) / 256, 256>>>(ei, ew, E);

    pullgemm_kernel<<<296, 256, SM_WORDS * 4>>>(x0, bias, out, N);
}

// round 15
// speedup vs baseline: 1.4706x; 1.4706x over previous
#include <cuda_runtime.h>
#include <cuda_bf16.h>
#include <cuda_fp16.h>
#include <cstdint>

#define D 128
#define OUTD 128
#define MAXN 100000
#define EPS 0.1f
#define CAP 48        // per-dst bucket capacity (avg in-degree 6.4)
#define OVFCAP 262144 // overflow list capacity (correctness fallback)

// Scratch (allocation-free rule: __device__ globals)
__device__ __half  g_agg_h[(size_t)MAXN * D];  // relu(EPS*x0 + sum), fp16
__device__ __half  g_x_h[(size_t)MAXN * D];
__device__ float   g_alpha_l[MAXN];
__device__ float   g_alpha_r[MAXN];
__device__ int     g_is64;
__device__ uint32_t g_W_hi[128 * 64];   // bf16x2 packed, [n][k/2]
__device__ uint32_t g_W_lo[128 * 64];
__device__ int     g_cnt[MAXN];
__device__ uint2   g_bucket[(size_t)MAXN * CAP];  // (src, coeff bits)
__device__ int     g_ovf_cnt;
__device__ uint4   g_ovf[OVFCAP];                 // (dst, src, coeff bits, 0)

// ---------------------------------------------------------------------------
// Kernel 1: fused alpha + prep (validated in R14: 17.4us).
// blocks [0, ablocks): alpha logits + fp16 copy of x (warp per node)
// blocks [ablocks, +32): W -> bf16 hi/lo; [.., +nzero): zero cnt;
// last block: int64/int32 detect + zero overflow counter.
// ---------------------------------------------------------------------------
__global__ void alpha_prep_kernel(const float* __restrict__ x,
                                  const float* __restrict__ att_l,
                                  const float* __restrict__ att_r,
                                  const float* __restrict__ W,
                                  const unsigned int* __restrict__ ei_words,
                                  int N, int E, int ablocks, int nzero) {
    int b = blockIdx.x;
    if (b < ablocks) {
        int warp = b * 8 + ((int)threadIdx.x >> 5);
        int lane = threadIdx.x & 31;
        if (warp >= N) return;

        float4 xv = reinterpret_cast<const float4*>(x + (size_t)warp * D)[lane];
        float4 al = reinterpret_cast<const float4*>(att_l)[lane];
        float4 ar = reinterpret_cast<const float4*>(att_r)[lane];

        float sl = xv.x * al.x + xv.y * al.y + xv.z * al.z + xv.w * al.w;
        float sr = xv.x * ar.x + xv.y * ar.y + xv.z * ar.z + xv.w * ar.w;
#pragma unroll
        for (int o = 16; o > 0; o >>= 1) {
            sl += __shfl_xor_sync(0xffffffffu, sl, o);
            sr += __shfl_xor_sync(0xffffffffu, sr, o);
        }
        if (lane == 0) {
            g_alpha_l[warp] = sl;
            g_alpha_r[warp] = sr;
        }

        __half2 h01 = __floats2half2_rn(xv.x, xv.y);
        __half2 h23 = __floats2half2_rn(xv.z, xv.w);
        uint2 hw = make_uint2(*reinterpret_cast<uint32_t*>(&h01),
                              *reinterpret_cast<uint32_t*>(&h23));
        reinterpret_cast<uint2*>(g_x_h + (size_t)warp * D)[lane] = hw;
    } else if (b < ablocks + 32) {
        int idx = (b - ablocks) * 256 + threadIdx.x;  // < 8192
        int n = idx >> 6, k2 = idx & 63;
        float w0 = W[n * D + 2 * k2];
        float w1 = W[n * D + 2 * k2 + 1];
        __nv_bfloat16 h0 = __float2bfloat16_rn(w0);
        __nv_bfloat16 h1 = __float2bfloat16_rn(w1);
        float l0 = w0 - __bfloat162float(h0);
        float l1 = w1 - __bfloat162float(h1);
        __nv_bfloat162 hp = __halves2bfloat162(h0, h1);
        __nv_bfloat162 lp = __halves2bfloat162(__float2bfloat16_rn(l0),
                                               __float2bfloat16_rn(l1));
        g_W_hi[idx] = *reinterpret_cast<uint32_t*>(&hp);
        g_W_lo[idx] = *reinterpret_cast<uint32_t*>(&lp);
    } else if (b < ablocks + 32 + nzero) {
        int i = (b - ablocks - 32) * 256 + threadIdx.x;
        if (i < N) g_cnt[i] = 0;
    } else {
        __shared__ int bad;
        if (threadIdx.x == 0) { bad = 0; g_ovf_cnt = 0; }
        __syncthreads();
        int nchk = E < 1024 ? E : 1024;
        for (int k = threadIdx.x; k < nchk; k += blockDim.x)
            if (ei_words[2 * k + 1] != 0u) bad = 1;
        __syncthreads();
        if (threadIdx.x == 0) g_is64 = bad ? 0 : 1;
    }
}

// ---------------------------------------------------------------------------
// Kernel 2: fill per-dst buckets with (src, coeff). Thread per edge.
// ---------------------------------------------------------------------------
__global__ void fill_kernel(const void* __restrict__ ei_raw,
                            const float* __restrict__ ew,
                            int E) {
    int e = blockIdx.x * blockDim.x + threadIdx.x;
    if (e >= E) return;

    int src, dst;
    if (g_is64) {
        const long long* ei = (const long long*)ei_raw;
        src = (int)ei[e];
        dst = (int)ei[(size_t)E + e];
    } else {
        const int* ei = (const int*)ei_raw;
        src = ei[e];
        dst = ei[(size_t)E + e];
    }
    float c = tanhf(g_alpha_l[src] + g_alpha_r[dst]) * ew[e];

    int slot = atomicAdd(&g_cnt[dst], 1);
    if (slot < CAP) {
        g_bucket[(size_t)dst * CAP + slot] = make_uint2((unsigned)src, __float_as_uint(c));
    } else {
        int o = atomicAdd(&g_ovf_cnt, 1);
        if (o < OVFCAP)
            g_ovf[o] = make_uint4((unsigned)dst, (unsigned)src, __float_as_uint(c), 0u);
    }
}

// ---------------------------------------------------------------------------
// Kernel 3: pull. Warp per dst node; bucket processed in chunks of 8 with
// CLAMPED indices; 8 independent entry loads + 8 independent gathers in
// flight. Stores relu(EPS*x0 + sum) as fp16 (half the write stream of fp32).
// ---------------------------------------------------------------------------
__global__ void pull_kernel(const float* __restrict__ x0, int N) {
    int node = (blockIdx.x * blockDim.x + threadIdx.x) >> 5;
    int lane = threadIdx.x & 31;
    if (node >= N) return;

    // issue x0 load first: independent of everything below
    float4 x0v = reinterpret_cast<const float4*>(x0 + (size_t)node * D)[lane];

    int cntr = g_cnt[node];
    int cnt = cntr > CAP ? CAP : cntr;

    const uint2* b = g_bucket + (size_t)node * CAP;
    float ax = 0.f, ay = 0.f, az = 0.f, aw = 0.f;

    for (int j0 = 0; j0 < cnt; j0 += 8) {
        uint2 pe[8];
        uint2 hw[8];
#pragma unroll
        for (int i = 0; i < 8; i++) {
            int jc = j0 + i;
            if (jc > cnt - 1) jc = cnt - 1;   // always valid (cnt >= 1 here)
            pe[i] = b[jc];
            if (j0 + i >= cnt) pe[i].y = 0u;  // zero coeff for inactive slot
        }
#pragma unroll
        for (int i = 0; i < 8; i++)
            hw[i] = reinterpret_cast<const uint2*>(g_x_h + (size_t)pe[i].x * D)[lane];
#pragma unroll
        for (int i = 0; i < 8; i++) {
            float c = __uint_as_float(pe[i].y);
            float2 f01 = __half22float2(*reinterpret_cast<__half2*>(&hw[i].x));
            float2 f23 = __half22float2(*reinterpret_cast<__half2*>(&hw[i].y));
            ax = fmaf(c, f01.x, ax);
            ay = fmaf(c, f01.y, ay);
            az = fmaf(c, f23.x, az);
            aw = fmaf(c, f23.y, aw);
        }
    }

    if (cntr > CAP) {  // essentially-never: scan overflow list for this node
        int novf = g_ovf_cnt;
        if (novf > OVFCAP) novf = OVFCAP;
        for (int k = 0; k < novf; k++) {
            uint4 e = g_ovf[k];
            if (e.x == (unsigned)node) {
                float c = __uint_as_float(e.z);
                uint2 hw = reinterpret_cast<const uint2*>(g_x_h + (size_t)e.y * D)[lane];
                float2 f01 = __half22float2(*reinterpret_cast<__half2*>(&hw.x));
                float2 f23 = __half22float2(*reinterpret_cast<__half2*>(&hw.y));
                ax = fmaf(c, f01.x, ax);
                ay = fmaf(c, f01.y, ay);
                az = fmaf(c, f23.x, az);
                aw = fmaf(c, f23.y, aw);
            }
        }
    }

    float o0 = fmaxf(fmaf(EPS, x0v.x, ax), 0.f);
    float o1 = fmaxf(fmaf(EPS, x0v.y, ay), 0.f);
    float o2 = fmaxf(fmaf(EPS, x0v.z, az), 0.f);
    float o3 = fmaxf(fmaf(EPS, x0v.w, aw), 0.f);

    __half2 p01 = __floats2half2_rn(o0, o1);
    __half2 p23 = __floats2half2_rn(o2, o3);
    uint2 ov = make_uint2(*reinterpret_cast<uint32_t*>(&p01),
                          *reinterpret_cast<uint32_t*>(&p23));
    reinterpret_cast<uint2*>(g_agg_h + (size_t)node * D)[lane] = ov;
}

// ---------------------------------------------------------------------------
// Kernel 4: out = agg @ W^T + b via bf16x3 mma.m16n8k16, 2 CTAs/SM.
// A read as fp16 (25.6 MB), converted to bf16 hi/lo in the tile fill.
// ---------------------------------------------------------------------------
#define PITCH 68   // words per row (64 + 4 pad)

#define SM_WHI 0
#define SM_WLO (128 * PITCH)
#define SM_AHI (2 * 128 * PITCH)
#define SM_ALO (2 * 128 * PITCH + 64 * PITCH)
#define SM_WORDS (2 * 128 * PITCH + 2 * 64 * PITCH)

__device__ __forceinline__ void mma_bf16(float* d, const uint32_t* a, const uint32_t* b) {
    asm volatile(
        "mma.sync.aligned.m16n8k16.row.col.f32.bf16.bf16.f32 "
        "{%0,%1,%2,%3}, {%4,%5,%6,%7}, {%8,%9}, {%0,%1,%2,%3};"
        : "+f"(d[0]), "+f"(d[1]), "+f"(d[2]), "+f"(d[3])
        : "r"(a[0]), "r"(a[1]), "r"(a[2]), "r"(a[3]), "r"(b[0]), "r"(b[1]));
}

__global__ __launch_bounds__(256, 2)
void gemm_kernel(const float* __restrict__ bias,
                 float* __restrict__ out,
                 int N) {
    extern __shared__ uint32_t sm[];
    int tid = threadIdx.x;
    int lane = tid & 31;
    int wid = tid >> 5;
    int warpM = wid >> 2;
    int warpN = wid & 3;

    for (int i = tid; i < 128 * 16; i += 256) {
        int r = i >> 4;
        int c4 = i & 15;
        uint4 h = reinterpret_cast<const uint4*>(g_W_hi)[(size_t)r * 16 + c4];
        uint4 l = reinterpret_cast<const uint4*>(g_W_lo)[(size_t)r * 16 + c4];
        *reinterpret_cast<uint4*>(&sm[SM_WHI + r * PITCH + c4 * 4]) = h;
        *reinterpret_cast<uint4*>(&sm[SM_WLO + r * PITCH + c4 * 4]) = l;
    }

    float bv[4][2];
#pragma unroll
    for (int nt = 0; nt < 4; nt++) {
        int col = warpN * 32 + nt * 8 + (lane & 3) * 2;
        bv[nt][0] = bias[col];
        bv[nt][1] = bias[col + 1];
    }
    __syncthreads();

    int ntiles = (N + 63) >> 6;
    for (int t = blockIdx.x; t < ntiles; t += gridDim.x) {
        int m0 = t << 6;

        // fill A tile: fp16 read -> bf16 hi/lo split
        for (int i = tid; i < 64 * 32; i += 256) {
            int r = i >> 5;
            int c4 = i & 31;           // 4 halves per chunk
            int row = m0 + r;
            float v0, v1, v2, v3;
            if (row < N) {
                uint2 hv = *reinterpret_cast<const uint2*>(
                    g_agg_h + (size_t)row * D + c4 * 4);
                float2 f01 = __half22float2(*reinterpret_cast<__half2*>(&hv.x));
                float2 f23 = __half22float2(*reinterpret_cast<__half2*>(&hv.y));
                v0 = f01.x; v1 = f01.y; v2 = f23.x; v3 = f23.y;
            } else {
                v0 = v1 = v2 = v3 = 0.f;
            }
            __nv_bfloat16 h0 = __float2bfloat16_rn(v0);
            __nv_bfloat16 h1 = __float2bfloat16_rn(v1);
            __nv_bfloat16 h2 = __float2bfloat16_rn(v2);
            __nv_bfloat16 h3 = __float2bfloat16_rn(v3);
            __nv_bfloat162 hp0 = __halves2bfloat162(h0, h1);
            __nv_bfloat162 hp1 = __halves2bfloat162(h2, h3);
            __nv_bfloat162 lp0 = __halves2bfloat162(
                __float2bfloat16_rn(v0 - __bfloat162float(h0)),
                __float2bfloat16_rn(v1 - __bfloat162float(h1)));
            __nv_bfloat162 lp1 = __halves2bfloat162(
                __float2bfloat16_rn(v2 - __bfloat162float(h2)),
                __float2bfloat16_rn(v3 - __bfloat162float(h3)));
            uint2 hw = make_uint2(*reinterpret_cast<uint32_t*>(&hp0),
                                  *reinterpret_cast<uint32_t*>(&hp1));
            uint2 lw = make_uint2(*reinterpret_cast<uint32_t*>(&lp0),
                                  *reinterpret_cast<uint32_t*>(&lp1));
            *reinterpret_cast<uint2*>(&sm[SM_AHI + r * PITCH + c4 * 2]) = hw;
            *reinterpret_cast<uint2*>(&sm[SM_ALO + r * PITCH + c4 * 2]) = lw;
        }
        __syncthreads();

        float acc[2][4][4];
#pragma unroll
        for (int mt = 0; mt < 2; mt++)
#pragma unroll
            for (int nt = 0; nt < 4; nt++)
#pragma unroll
                for (int i = 0; i < 4; i++) acc[mt][nt][i] = 0.f;

#pragma unroll
        for (int ks = 0; ks < 8; ks++) {
            int w0 = ks * 8 + (lane & 3);
            uint32_t ahi[2][4], alo[2][4];
#pragma unroll
            for (int mt = 0; mt < 2; mt++) {
                int r = warpM * 32 + mt * 16 + (lane >> 2);
                ahi[mt][0] = sm[SM_AHI + r * PITCH + w0];
                ahi[mt][1] = sm[SM_AHI + (r + 8) * PITCH + w0];
                ahi[mt][2] = sm[SM_AHI + r * PITCH + w0 + 4];
                ahi[mt][3] = sm[SM_AHI + (r + 8) * PITCH + w0 + 4];
                alo[mt][0] = sm[SM_ALO + r * PITCH + w0];
                alo[mt][1] = sm[SM_ALO + (r + 8) * PITCH + w0];
                alo[mt][2] = sm[SM_ALO + r * PITCH + w0 + 4];
                alo[mt][3] = sm[SM_ALO + (r + 8) * PITCH + w0 + 4];
            }
            uint32_t bhi[4][2], blo[4][2];
#pragma unroll
            for (int nt = 0; nt < 4; nt++) {
                int n = warpN * 32 + nt * 8 + (lane >> 2);
                bhi[nt][0] = sm[SM_WHI + n * PITCH + w0];
                bhi[nt][1] = sm[SM_WHI + n * PITCH + w0 + 4];
                blo[nt][0] = sm[SM_WLO + n * PITCH + w0];
                blo[nt][1] = sm[SM_WLO + n * PITCH + w0 + 4];
            }
#pragma unroll
            for (int mt = 0; mt < 2; mt++)
#pragma unroll
                for (int nt = 0; nt < 4; nt++) {
                    mma_bf16(acc[mt][nt], ahi[mt], blo[nt]);
                    mma_bf16(acc[mt][nt], alo[mt], bhi[nt]);
                    mma_bf16(acc[mt][nt], ahi[mt], bhi[nt]);
                }
        }

#pragma unroll
        for (int mt = 0; mt < 2; mt++) {
            int r0 = m0 + warpM * 32 + mt * 16 + (lane >> 2);
#pragma unroll
            for (int nt = 0; nt < 4; nt++) {
                int col = warpN * 32 + nt * 8 + (lane & 3) * 2;
                if (r0 < N) {
                    float2 v = make_float2(acc[mt][nt][0] + bv[nt][0],
                                           acc[mt][nt][1] + bv[nt][1]);
                    *reinterpret_cast<float2*>(out + (size_t)r0 * OUTD + col) = v;
                }
                if (r0 + 8 < N) {
                    float2 v = make_float2(acc[mt][nt][2] + bv[nt][0],
                                           acc[mt][nt][3] + bv[nt][1]);
                    *reinterpret_cast<float2*>(out + (size_t)(r0 + 8) * OUTD + col) = v;
                }
            }
        }
        __syncthreads();
    }
}

// ---------------------------------------------------------------------------
// Launch: 4 kernels. alpha+prep -> fill -> pull -> gemm.
// ---------------------------------------------------------------------------
extern "C" void kernel_launch(void* const* d_in, const int* in_sizes, int n_in,
                              void* d_out, int out_size) {
    const float* x      = (const float*)d_in[0];
    const float* x0     = (const float*)d_in[1];
    const float* ew     = (const float*)d_in[2];
    const float* att_l  = (const float*)d_in[3];
    const float* att_r  = (const float*)d_in[4];
    const float* W      = (const float*)d_in[5];
    const float* bias   = (const float*)d_in[6];
    const void*  ei     = (const void*)d_in[7];
    float* out = (float*)d_out;

    int N = in_sizes[1] / D;
    int E = in_sizes[2];

    static bool attr_set = false;
    if (!attr_set) {
        cudaFuncSetAttribute(gemm_kernel,
                             cudaFuncAttributeMaxDynamicSharedMemorySize,
                             SM_WORDS * 4);
        attr_set = true;
    }

    int ablocks = (N + 7) / 8;
    int nzero = (N + 255) / 256;
    alpha_prep_kernel<<<ablocks + 32 + nzero + 1, 256>>>(
        x, att_l, att_r, W, (const unsigned int*)ei, N, E, ablocks, nzero);

    fill_kernel<<<(E + 255) / 256, 256>>>(ei, ew, E);

    {
        int blocks = (N + 7) / 8;
        pull_kernel<<<blocks, 256>>>(x0, N);
    }

    gemm_kernel<<<296, 256, SM_WORDS * 4>>>(bias, out, N);
}

// round 16
// speedup vs baseline: 1.4995x; 1.0197x over previous
#include <cuda_runtime.h>
#include <cuda_bf16.h>
#include <cuda_fp16.h>
#include <cstdint>

#define D 128
#define OUTD 128
#define MAXN 100000
#define EPS 0.1f
#define CAP 48        // per-dst bucket capacity (avg in-degree 6.4)
#define OVFCAP 262144 // overflow list capacity (correctness fallback)

// Scratch (allocation-free rule: __device__ globals)
__device__ __half  g_agg_h[(size_t)MAXN * D];  // relu(EPS*x0 + sum), fp16
__device__ __half  g_x_h[(size_t)MAXN * D];
__device__ float   g_alpha_l[MAXN];
__device__ float   g_alpha_r[MAXN];
__device__ int     g_is64;
__device__ uint32_t g_W_hi[128 * 64];   // fp16x2 packed, [n][k/2]
__device__ uint32_t g_W_lo[128 * 64];   // fp16 residual
__device__ int     g_cnt[MAXN];
__device__ uint2   g_bucket[(size_t)MAXN * CAP];  // (src, coeff bits)
__device__ int     g_ovf_cnt;
__device__ uint4   g_ovf[OVFCAP];                 // (dst, src, coeff bits, 0)

// ---------------------------------------------------------------------------
// Kernel 1: fused alpha + prep.
// blocks [0, ablocks): alpha logits + fp16 copy of x (warp per node)
// blocks [ablocks, +32): W -> fp16 hi/lo; [.., +nzero): zero cnt;
// last block: int64/int32 detect + zero overflow counter.
// ---------------------------------------------------------------------------
__global__ void alpha_prep_kernel(const float* __restrict__ x,
                                  const float* __restrict__ att_l,
                                  const float* __restrict__ att_r,
                                  const float* __restrict__ W,
                                  const unsigned int* __restrict__ ei_words,
                                  int N, int E, int ablocks, int nzero) {
    int b = blockIdx.x;
    if (b < ablocks) {
        int warp = b * 8 + ((int)threadIdx.x >> 5);
        int lane = threadIdx.x & 31;
        if (warp >= N) return;

        float4 xv = reinterpret_cast<const float4*>(x + (size_t)warp * D)[lane];
        float4 al = reinterpret_cast<const float4*>(att_l)[lane];
        float4 ar = reinterpret_cast<const float4*>(att_r)[lane];

        float sl = xv.x * al.x + xv.y * al.y + xv.z * al.z + xv.w * al.w;
        float sr = xv.x * ar.x + xv.y * ar.y + xv.z * ar.z + xv.w * ar.w;
#pragma unroll
        for (int o = 16; o > 0; o >>= 1) {
            sl += __shfl_xor_sync(0xffffffffu, sl, o);
            sr += __shfl_xor_sync(0xffffffffu, sr, o);
        }
        if (lane == 0) {
            g_alpha_l[warp] = sl;
            g_alpha_r[warp] = sr;
        }

        __half2 h01 = __floats2half2_rn(xv.x, xv.y);
        __half2 h23 = __floats2half2_rn(xv.z, xv.w);
        uint2 hw = make_uint2(*reinterpret_cast<uint32_t*>(&h01),
                              *reinterpret_cast<uint32_t*>(&h23));
        reinterpret_cast<uint2*>(g_x_h + (size_t)warp * D)[lane] = hw;
    } else if (b < ablocks + 32) {
        int idx = (b - ablocks) * 256 + threadIdx.x;  // < 8192
        int n = idx >> 6, k2 = idx & 63;
        float w0 = W[n * D + 2 * k2];
        float w1 = W[n * D + 2 * k2 + 1];
        __half h0 = __float2half_rn(w0);
        __half h1 = __float2half_rn(w1);
        float l0 = w0 - __half2float(h0);
        float l1 = w1 - __half2float(h1);
        __half2 hp = __halves2half2(h0, h1);
        __half2 lp = __halves2half2(__float2half_rn(l0), __float2half_rn(l1));
        g_W_hi[idx] = *reinterpret_cast<uint32_t*>(&hp);
        g_W_lo[idx] = *reinterpret_cast<uint32_t*>(&lp);
    } else if (b < ablocks + 32 + nzero) {
        int i = (b - ablocks - 32) * 256 + threadIdx.x;
        if (i < N) g_cnt[i] = 0;
    } else {
        __shared__ int bad;
        if (threadIdx.x == 0) { bad = 0; g_ovf_cnt = 0; }
        __syncthreads();
        int nchk = E < 1024 ? E : 1024;
        for (int k = threadIdx.x; k < nchk; k += blockDim.x)
            if (ei_words[2 * k + 1] != 0u) bad = 1;
        __syncthreads();
        if (threadIdx.x == 0) g_is64 = bad ? 0 : 1;
    }
}

// ---------------------------------------------------------------------------
// Kernel 2: fill per-dst buckets with (src, coeff). Thread per edge.
// ---------------------------------------------------------------------------
__global__ void fill_kernel(const void* __restrict__ ei_raw,
                            const float* __restrict__ ew,
                            int E) {
    int e = blockIdx.x * blockDim.x + threadIdx.x;
    if (e >= E) return;

    int src, dst;
    if (g_is64) {
        const long long* ei = (const long long*)ei_raw;
        src = (int)ei[e];
        dst = (int)ei[(size_t)E + e];
    } else {
        const int* ei = (const int*)ei_raw;
        src = ei[e];
        dst = ei[(size_t)E + e];
    }
    float c = tanhf(g_alpha_l[src] + g_alpha_r[dst]) * ew[e];

    int slot = atomicAdd(&g_cnt[dst], 1);
    if (slot < CAP) {
        g_bucket[(size_t)dst * CAP + slot] = make_uint2((unsigned)src, __float_as_uint(c));
    } else {
        int o = atomicAdd(&g_ovf_cnt, 1);
        if (o < OVFCAP)
            g_ovf[o] = make_uint4((unsigned)dst, (unsigned)src, __float_as_uint(c), 0u);
    }
}

// ---------------------------------------------------------------------------
// Kernel 3: pull. Warp per dst node; 8-deep MLP bucket loop with clamped
// indices. Stores relu(EPS*x0 + sum) as fp16.
// ---------------------------------------------------------------------------
__global__ void pull_kernel(const float* __restrict__ x0, int N) {
    int node = (blockIdx.x * blockDim.x + threadIdx.x) >> 5;
    int lane = threadIdx.x & 31;
    if (node >= N) return;

    float4 x0v = reinterpret_cast<const float4*>(x0 + (size_t)node * D)[lane];

    int cntr = g_cnt[node];
    int cnt = cntr > CAP ? CAP : cntr;

    const uint2* b = g_bucket + (size_t)node * CAP;
    float ax = 0.f, ay = 0.f, az = 0.f, aw = 0.f;

    for (int j0 = 0; j0 < cnt; j0 += 8) {
        uint2 pe[8];
        uint2 hw[8];
#pragma unroll
        for (int i = 0; i < 8; i++) {
            int jc = j0 + i;
            if (jc > cnt - 1) jc = cnt - 1;   // always valid (cnt >= 1 here)
            pe[i] = b[jc];
            if (j0 + i >= cnt) pe[i].y = 0u;  // zero coeff for inactive slot
        }
#pragma unroll
        for (int i = 0; i < 8; i++)
            hw[i] = reinterpret_cast<const uint2*>(g_x_h + (size_t)pe[i].x * D)[lane];
#pragma unroll
        for (int i = 0; i < 8; i++) {
            float c = __uint_as_float(pe[i].y);
            float2 f01 = __half22float2(*reinterpret_cast<__half2*>(&hw[i].x));
            float2 f23 = __half22float2(*reinterpret_cast<__half2*>(&hw[i].y));
            ax = fmaf(c, f01.x, ax);
            ay = fmaf(c, f01.y, ay);
            az = fmaf(c, f23.x, az);
            aw = fmaf(c, f23.y, aw);
        }
    }

    if (cntr > CAP) {  // essentially-never: scan overflow list for this node
        int novf = g_ovf_cnt;
        if (novf > OVFCAP) novf = OVFCAP;
        for (int k = 0; k < novf; k++) {
            uint4 e = g_ovf[k];
            if (e.x == (unsigned)node) {
                float c = __uint_as_float(e.z);
                uint2 hw = reinterpret_cast<const uint2*>(g_x_h + (size_t)e.y * D)[lane];
                float2 f01 = __half22float2(*reinterpret_cast<__half2*>(&hw.x));
                float2 f23 = __half22float2(*reinterpret_cast<__half2*>(&hw.y));
                ax = fmaf(c, f01.x, ax);
                ay = fmaf(c, f01.y, ay);
                az = fmaf(c, f23.x, az);
                aw = fmaf(c, f23.y, aw);
            }
        }
    }

    float o0 = fmaxf(fmaf(EPS, x0v.x, ax), 0.f);
    float o1 = fmaxf(fmaf(EPS, x0v.y, ay), 0.f);
    float o2 = fmaxf(fmaf(EPS, x0v.z, az), 0.f);
    float o3 = fmaxf(fmaf(EPS, x0v.w, aw), 0.f);

    __half2 p01 = __floats2half2_rn(o0, o1);
    __half2 p23 = __floats2half2_rn(o2, o3);
    uint2 ov = make_uint2(*reinterpret_cast<uint32_t*>(&p01),
                          *reinterpret_cast<uint32_t*>(&p23));
    reinterpret_cast<uint2*>(g_agg_h + (size_t)node * D)[lane] = ov;
}

// ---------------------------------------------------------------------------
// Kernel 4: out = A @ W^T + b via fp16 mma.m16n8k16 (fp32 accum), 2 CTAs/SM.
// A is exactly fp16 -> used directly (1 plane, pure copy in fill).
// W split into fp16 hi + fp16 lo (~22-bit effective mantissa): 2 mmas.
// ---------------------------------------------------------------------------
#define PITCH 68   // words per row (64 + 4 pad)

#define SM_WHI 0
#define SM_WLO (128 * PITCH)
#define SM_A   (2 * 128 * PITCH)
#define SM_WORDS (2 * 128 * PITCH + 64 * PITCH)

__device__ __forceinline__ void mma_f16(float* d, const uint32_t* a, const uint32_t* b) {
    asm volatile(
        "mma.sync.aligned.m16n8k16.row.col.f32.f16.f16.f32 "
        "{%0,%1,%2,%3}, {%4,%5,%6,%7}, {%8,%9}, {%0,%1,%2,%3};"
        : "+f"(d[0]), "+f"(d[1]), "+f"(d[2]), "+f"(d[3])
        : "r"(a[0]), "r"(a[1]), "r"(a[2]), "r"(a[3]), "r"(b[0]), "r"(b[1]));
}

__global__ __launch_bounds__(256, 2)
void gemm_kernel(const float* __restrict__ bias,
                 float* __restrict__ out,
                 int N) {
    extern __shared__ uint32_t sm[];
    int tid = threadIdx.x;
    int lane = tid & 31;
    int wid = tid >> 5;
    int warpM = wid >> 2;
    int warpN = wid & 3;

    for (int i = tid; i < 128 * 16; i += 256) {
        int r = i >> 4;
        int c4 = i & 15;
        uint4 h = reinterpret_cast<const uint4*>(g_W_hi)[(size_t)r * 16 + c4];
        uint4 l = reinterpret_cast<const uint4*>(g_W_lo)[(size_t)r * 16 + c4];
        *reinterpret_cast<uint4*>(&sm[SM_WHI + r * PITCH + c4 * 4]) = h;
        *reinterpret_cast<uint4*>(&sm[SM_WLO + r * PITCH + c4 * 4]) = l;
    }

    float bv[4][2];
#pragma unroll
    for (int nt = 0; nt < 4; nt++) {
        int col = warpN * 32 + nt * 8 + (lane & 3) * 2;
        bv[nt][0] = bias[col];
        bv[nt][1] = bias[col + 1];
    }
    __syncthreads();

    int ntiles = (N + 63) >> 6;
    for (int t = blockIdx.x; t < ntiles; t += gridDim.x) {
        int m0 = t << 6;

        // fill A tile: pure uint4 copy of fp16 rows (64 rows x 16 uint4)
        for (int i = tid; i < 64 * 16; i += 256) {
            int r = i >> 4;
            int c4 = i & 15;
            int row = m0 + r;
            uint4 v;
            if (row < N)
                v = *reinterpret_cast<const uint4*>(g_agg_h + (size_t)row * D + c4 * 8);
            else
                v = make_uint4(0u, 0u, 0u, 0u);
            *reinterpret_cast<uint4*>(&sm[SM_A + r * PITCH + c4 * 4]) = v;
        }
        __syncthreads();

        float acc[2][4][4];
#pragma unroll
        for (int mt = 0; mt < 2; mt++)
#pragma unroll
            for (int nt = 0; nt < 4; nt++)
#pragma unroll
                for (int i = 0; i < 4; i++) acc[mt][nt][i] = 0.f;

#pragma unroll
        for (int ks = 0; ks < 8; ks++) {
            int w0 = ks * 8 + (lane & 3);
            uint32_t a[2][4];
#pragma unroll
            for (int mt = 0; mt < 2; mt++) {
                int r = warpM * 32 + mt * 16 + (lane >> 2);
                a[mt][0] = sm[SM_A + r * PITCH + w0];
                a[mt][1] = sm[SM_A + (r + 8) * PITCH + w0];
                a[mt][2] = sm[SM_A + r * PITCH + w0 + 4];
                a[mt][3] = sm[SM_A + (r + 8) * PITCH + w0 + 4];
            }
            uint32_t bhi[4][2], blo[4][2];
#pragma unroll
            for (int nt = 0; nt < 4; nt++) {
                int n = warpN * 32 + nt * 8 + (lane >> 2);
                bhi[nt][0] = sm[SM_WHI + n * PITCH + w0];
                bhi[nt][1] = sm[SM_WHI + n * PITCH + w0 + 4];
                blo[nt][0] = sm[SM_WLO + n * PITCH + w0];
                blo[nt][1] = sm[SM_WLO + n * PITCH + w0 + 4];
            }
#pragma unroll
            for (int mt = 0; mt < 2; mt++)
#pragma unroll
                for (int nt = 0; nt < 4; nt++) {
                    mma_f16(acc[mt][nt], a[mt], blo[nt]);
                    mma_f16(acc[mt][nt], a[mt], bhi[nt]);
                }
        }

#pragma unroll
        for (int mt = 0; mt < 2; mt++) {
            int r0 = m0 + warpM * 32 + mt * 16 + (lane >> 2);
#pragma unroll
            for (int nt = 0; nt < 4; nt++) {
                int col = warpN * 32 + nt * 8 + (lane & 3) * 2;
                if (r0 < N) {
                    float2 v = make_float2(acc[mt][nt][0] + bv[nt][0],
                                           acc[mt][nt][1] + bv[nt][1]);
                    *reinterpret_cast<float2*>(out + (size_t)r0 * OUTD + col) = v;
                }
                if (r0 + 8 < N) {
                    float2 v = make_float2(acc[mt][nt][2] + bv[nt][0],
                                           acc[mt][nt][3] + bv[nt][1]);
                    *reinterpret_cast<float2*>(out + (size_t)(r0 + 8) * OUTD + col) = v;
                }
            }
        }
        __syncthreads();
    }
}

// ---------------------------------------------------------------------------
// Launch: 4 kernels. alpha+prep -> fill -> pull -> gemm.
// ---------------------------------------------------------------------------
extern "C" void kernel_launch(void* const* d_in, const int* in_sizes, int n_in,
                              void* d_out, int out_size) {
    const float* x      = (const float*)d_in[0];
    const float* x0     = (const float*)d_in[1];
    const float* ew     = (const float*)d_in[2];
    const float* att_l  = (const float*)d_in[3];
    const float* att_r  = (const float*)d_in[4];
    const float* W      = (const float*)d_in[5];
    const float* bias   = (const float*)d_in[6];
    const void*  ei     = (const void*)d_in[7];
    float* out = (float*)d_out;

    int N = in_sizes[1] / D;
    int E = in_sizes[2];

    static bool attr_set = false;
    if (!attr_set) {
        cudaFuncSetAttribute(gemm_kernel,
                             cudaFuncAttributeMaxDynamicSharedMemorySize,
                             SM_WORDS * 4);
        attr_set = true;
    }

    int ablocks = (N + 7) / 8;
    int nzero = (N + 255) / 256;
    alpha_prep_kernel<<<ablocks + 32 + nzero + 1, 256>>>(
        x, att_l, att_r, W, (const unsigned int*)ei, N, E, ablocks, nzero);

    fill_kernel<<<(E + 255) / 256, 256>>>(ei, ew, E);

    {
        int blocks = (N + 7) / 8;
        pull_kernel<<<blocks, 256>>>(x0, N);
    }

    gemm_kernel<<<296, 256, SM_WORDS * 4>>>(bias, out, N);
}

// round 17
// speedup vs baseline: 1.6232x; 1.0825x over previous
#include <cuda_runtime.h>
#include <cuda_bf16.h>
#include <cuda_fp16.h>
#include <cstdint>

#define D 128
#define OUTD 128
#define MAXN 100000
#define EPS 0.1f
#define CAP 48        // per-dst bucket capacity (avg in-degree 6.4)
#define OVFCAP 262144 // overflow list capacity (correctness fallback)

// Scratch (allocation-free rule: __device__ globals)
__device__ __half  g_agg_h[(size_t)MAXN * D];  // relu(EPS*x0 + sum), fp16
__device__ __half  g_x_h[(size_t)MAXN * D];
__device__ float   g_alpha_l[MAXN];
__device__ float   g_alpha_r[MAXN];
__device__ int     g_is64;
__device__ uint32_t g_W_hi[128 * 64];   // fp16x2 packed, [n][k/2]
__device__ uint32_t g_W_lo[128 * 64];   // fp16 residual
__device__ int     g_cnt[MAXN];
__device__ uint2   g_bucket[(size_t)MAXN * CAP];  // (src, coeff bits)
__device__ int     g_ovf_cnt;
__device__ uint4   g_ovf[OVFCAP];                 // (dst, src, coeff bits, 0)

// ---------------------------------------------------------------------------
// Kernel 1: fused alpha + prep.
// ---------------------------------------------------------------------------
__global__ void alpha_prep_kernel(const float* __restrict__ x,
                                  const float* __restrict__ att_l,
                                  const float* __restrict__ att_r,
                                  const float* __restrict__ W,
                                  const unsigned int* __restrict__ ei_words,
                                  int N, int E, int ablocks, int nzero) {
    int b = blockIdx.x;
    if (b < ablocks) {
        int warp = b * 8 + ((int)threadIdx.x >> 5);
        int lane = threadIdx.x & 31;
        if (warp >= N) return;

        float4 xv = reinterpret_cast<const float4*>(x + (size_t)warp * D)[lane];
        float4 al = reinterpret_cast<const float4*>(att_l)[lane];
        float4 ar = reinterpret_cast<const float4*>(att_r)[lane];

        float sl = xv.x * al.x + xv.y * al.y + xv.z * al.z + xv.w * al.w;
        float sr = xv.x * ar.x + xv.y * ar.y + xv.z * ar.z + xv.w * ar.w;
#pragma unroll
        for (int o = 16; o > 0; o >>= 1) {
            sl += __shfl_xor_sync(0xffffffffu, sl, o);
            sr += __shfl_xor_sync(0xffffffffu, sr, o);
        }
        if (lane == 0) {
            g_alpha_l[warp] = sl;
            g_alpha_r[warp] = sr;
        }

        __half2 h01 = __floats2half2_rn(xv.x, xv.y);
        __half2 h23 = __floats2half2_rn(xv.z, xv.w);
        uint2 hw = make_uint2(*reinterpret_cast<uint32_t*>(&h01),
                              *reinterpret_cast<uint32_t*>(&h23));
        reinterpret_cast<uint2*>(g_x_h + (size_t)warp * D)[lane] = hw;
    } else if (b < ablocks + 32) {
        int idx = (b - ablocks) * 256 + threadIdx.x;  // < 8192
        int n = idx >> 6, k2 = idx & 63;
        float w0 = W[n * D + 2 * k2];
        float w1 = W[n * D + 2 * k2 + 1];
        __half h0 = __float2half_rn(w0);
        __half h1 = __float2half_rn(w1);
        float l0 = w0 - __half2float(h0);
        float l1 = w1 - __half2float(h1);
        __half2 hp = __halves2half2(h0, h1);
        __half2 lp = __halves2half2(__float2half_rn(l0), __float2half_rn(l1));
        g_W_hi[idx] = *reinterpret_cast<uint32_t*>(&hp);
        g_W_lo[idx] = *reinterpret_cast<uint32_t*>(&lp);
    } else if (b < ablocks + 32 + nzero) {
        int i = (b - ablocks - 32) * 256 + threadIdx.x;
        if (i < N) g_cnt[i] = 0;
    } else {
        __shared__ int bad;
        if (threadIdx.x == 0) { bad = 0; g_ovf_cnt = 0; }
        __syncthreads();
        int nchk = E < 1024 ? E : 1024;
        for (int k = threadIdx.x; k < nchk; k += blockDim.x)
            if (ei_words[2 * k + 1] != 0u) bad = 1;
        __syncthreads();
        if (threadIdx.x == 0) g_is64 = bad ? 0 : 1;
    }
}

// ---------------------------------------------------------------------------
// Kernel 2: fill per-dst buckets with (src, coeff). Thread per edge.
// ---------------------------------------------------------------------------
__global__ void fill_kernel(const void* __restrict__ ei_raw,
                            const float* __restrict__ ew,
                            int E) {
    int e = blockIdx.x * blockDim.x + threadIdx.x;
    if (e >= E) return;

    int src, dst;
    if (g_is64) {
        const long long* ei = (const long long*)ei_raw;
        src = (int)ei[e];
        dst = (int)ei[(size_t)E + e];
    } else {
        const int* ei = (const int*)ei_raw;
        src = ei[e];
        dst = ei[(size_t)E + e];
    }
    float c = tanhf(g_alpha_l[src] + g_alpha_r[dst]) * ew[e];

    int slot = atomicAdd(&g_cnt[dst], 1);
    if (slot < CAP) {
        g_bucket[(size_t)dst * CAP + slot] = make_uint2((unsigned)src, __float_as_uint(c));
    } else {
        int o = atomicAdd(&g_ovf_cnt, 1);
        if (o < OVFCAP)
            g_ovf[o] = make_uint4((unsigned)dst, (unsigned)src, __float_as_uint(c), 0u);
    }
}

// ---------------------------------------------------------------------------
// Kernel 3: pull. Warp per dst node; 8-deep MLP bucket loop with clamped
// indices. Stores relu(EPS*x0 + sum) as fp16.
// ---------------------------------------------------------------------------
__global__ void pull_kernel(const float* __restrict__ x0, int N) {
    int node = (blockIdx.x * blockDim.x + threadIdx.x) >> 5;
    int lane = threadIdx.x & 31;
    if (node >= N) return;

    float4 x0v = reinterpret_cast<const float4*>(x0 + (size_t)node * D)[lane];

    int cntr = g_cnt[node];
    int cnt = cntr > CAP ? CAP : cntr;

    const uint2* b = g_bucket + (size_t)node * CAP;
    float ax = 0.f, ay = 0.f, az = 0.f, aw = 0.f;

    for (int j0 = 0; j0 < cnt; j0 += 8) {
        uint2 pe[8];
        uint2 hw[8];
#pragma unroll
        for (int i = 0; i < 8; i++) {
            int jc = j0 + i;
            if (jc > cnt - 1) jc = cnt - 1;   // always valid (cnt >= 1 here)
            pe[i] = b[jc];
            if (j0 + i >= cnt) pe[i].y = 0u;  // zero coeff for inactive slot
        }
#pragma unroll
        for (int i = 0; i < 8; i++)
            hw[i] = reinterpret_cast<const uint2*>(g_x_h + (size_t)pe[i].x * D)[lane];
#pragma unroll
        for (int i = 0; i < 8; i++) {
            float c = __uint_as_float(pe[i].y);
            float2 f01 = __half22float2(*reinterpret_cast<__half2*>(&hw[i].x));
            float2 f23 = __half22float2(*reinterpret_cast<__half2*>(&hw[i].y));
            ax = fmaf(c, f01.x, ax);
            ay = fmaf(c, f01.y, ay);
            az = fmaf(c, f23.x, az);
            aw = fmaf(c, f23.y, aw);
        }
    }

    if (cntr > CAP) {  // essentially-never: scan overflow list for this node
        int novf = g_ovf_cnt;
        if (novf > OVFCAP) novf = OVFCAP;
        for (int k = 0; k < novf; k++) {
            uint4 e = g_ovf[k];
            if (e.x == (unsigned)node) {
                float c = __uint_as_float(e.z);
                uint2 hw = reinterpret_cast<const uint2*>(g_x_h + (size_t)e.y * D)[lane];
                float2 f01 = __half22float2(*reinterpret_cast<__half2*>(&hw.x));
                float2 f23 = __half22float2(*reinterpret_cast<__half2*>(&hw.y));
                ax = fmaf(c, f01.x, ax);
                ay = fmaf(c, f01.y, ay);
                az = fmaf(c, f23.x, az);
                aw = fmaf(c, f23.y, aw);
            }
        }
    }

    float o0 = fmaxf(fmaf(EPS, x0v.x, ax), 0.f);
    float o1 = fmaxf(fmaf(EPS, x0v.y, ay), 0.f);
    float o2 = fmaxf(fmaf(EPS, x0v.z, az), 0.f);
    float o3 = fmaxf(fmaf(EPS, x0v.w, aw), 0.f);

    __half2 p01 = __floats2half2_rn(o0, o1);
    __half2 p23 = __floats2half2_rn(o2, o3);
    uint2 ov = make_uint2(*reinterpret_cast<uint32_t*>(&p01),
                          *reinterpret_cast<uint32_t*>(&p23));
    reinterpret_cast<uint2*>(g_agg_h + (size_t)node * D)[lane] = ov;
}

// ---------------------------------------------------------------------------
// Kernel 4: out = A @ W^T + b via fp16 mma.m16n8k16 (fp32 accum), 2 CTAs/SM.
// Double-buffered A tiles via cp.async: fill latency hidden behind mma.
// ---------------------------------------------------------------------------
#define PITCH 68   // words per row (64 + 4 pad)

#define SM_WHI 0
#define SM_WLO (128 * PITCH)
#define SM_A0  (2 * 128 * PITCH)
#define SM_A1  (2 * 128 * PITCH + 64 * PITCH)
#define SM_WORDS (2 * 128 * PITCH + 2 * 64 * PITCH)

__device__ __forceinline__ void mma_f16(float* d, const uint32_t* a, const uint32_t* b) {
    asm volatile(
        "mma.sync.aligned.m16n8k16.row.col.f32.f16.f16.f32 "
        "{%0,%1,%2,%3}, {%4,%5,%6,%7}, {%8,%9}, {%0,%1,%2,%3};"
        : "+f"(d[0]), "+f"(d[1]), "+f"(d[2]), "+f"(d[3])
        : "r"(a[0]), "r"(a[1]), "r"(a[2]), "r"(a[3]), "r"(b[0]), "r"(b[1]));
}

__device__ __forceinline__ void cp_async16(uint32_t smem_addr, const void* gptr,
                                           int src_bytes) {
    asm volatile("cp.async.cg.shared.global [%0], [%1], 16, %2;"
                 :: "r"(smem_addr), "l"(gptr), "r"(src_bytes) : "memory");
}
#define CP_COMMIT() asm volatile("cp.async.commit_group;" ::: "memory")
#define CP_WAIT1()  asm volatile("cp.async.wait_group 1;" ::: "memory")

__global__ __launch_bounds__(256, 2)
void gemm_kernel(const float* __restrict__ bias,
                 float* __restrict__ out,
                 int N) {
    extern __shared__ uint32_t sm[];
    uint32_t smem_base = (uint32_t)__cvta_generic_to_shared(sm);
    int tid = threadIdx.x;
    int lane = tid & 31;
    int wid = tid >> 5;
    int warpM = wid >> 2;
    int warpN = wid & 3;

    // ---- load packed W hi/lo into smem once ----
    for (int i = tid; i < 128 * 16; i += 256) {
        int r = i >> 4;
        int c4 = i & 15;
        uint4 h = reinterpret_cast<const uint4*>(g_W_hi)[(size_t)r * 16 + c4];
        uint4 l = reinterpret_cast<const uint4*>(g_W_lo)[(size_t)r * 16 + c4];
        *reinterpret_cast<uint4*>(&sm[SM_WHI + r * PITCH + c4 * 4]) = h;
        *reinterpret_cast<uint4*>(&sm[SM_WLO + r * PITCH + c4 * 4]) = l;
    }

    float bv[4][2];
#pragma unroll
    for (int nt = 0; nt < 4; nt++) {
        int col = warpN * 32 + nt * 8 + (lane & 3) * 2;
        bv[nt][0] = bias[col];
        bv[nt][1] = bias[col + 1];
    }

    int ntiles = (N + 63) >> 6;
    int g = gridDim.x;

    // prefetch helper: tile t into buffer (SM_A0 or SM_A1)
    // 64 rows x 16 cp.async(16B) = 1024 ops / 256 threads = 4 per thread
    auto prefetch = [&](int t, uint32_t bufoff) {
        if (t < ntiles) {
            int m0 = t << 6;
#pragma unroll
            for (int k = 0; k < 4; k++) {
                int i = tid + k * 256;      // 0..1023
                int r = i >> 4;
                int c4 = i & 15;
                int row = m0 + r;
                int rowc = row < N ? row : 0;
                const void* gp = (const void*)(g_agg_h + (size_t)rowc * D + c4 * 8);
                cp_async16(smem_base + (bufoff + r * PITCH + c4 * 4) * 4, gp,
                           row < N ? 16 : 0);
            }
        }
        CP_COMMIT();  // always commit (possibly empty group) to keep counts aligned
    };

    int t0 = blockIdx.x;
    prefetch(t0, SM_A0);
    prefetch(t0 + g, SM_A1);

    int bufsel = 0;
    for (int t = t0; t < ntiles; t += g, bufsel ^= 1) {
        uint32_t aoff = bufsel ? SM_A1 : SM_A0;

        CP_WAIT1();          // current buffer's group done (one younger pending)
        __syncthreads();     // make cp.async data visible to all warps (also covers W load on first iter)

        float acc[2][4][4];
#pragma unroll
        for (int mt = 0; mt < 2; mt++)
#pragma unroll
            for (int nt = 0; nt < 4; nt++)
#pragma unroll
                for (int i = 0; i < 4; i++) acc[mt][nt][i] = 0.f;

#pragma unroll
        for (int ks = 0; ks < 8; ks++) {
            int w0 = ks * 8 + (lane & 3);
            uint32_t a[2][4];
#pragma unroll
            for (int mt = 0; mt < 2; mt++) {
                int r = warpM * 32 + mt * 16 + (lane >> 2);
                a[mt][0] = sm[aoff + r * PITCH + w0];
                a[mt][1] = sm[aoff + (r + 8) * PITCH + w0];
                a[mt][2] = sm[aoff + r * PITCH + w0 + 4];
                a[mt][3] = sm[aoff + (r + 8) * PITCH + w0 + 4];
            }
            uint32_t bhi[4][2], blo[4][2];
#pragma unroll
            for (int nt = 0; nt < 4; nt++) {
                int n = warpN * 32 + nt * 8 + (lane >> 2);
                bhi[nt][0] = sm[SM_WHI + n * PITCH + w0];
                bhi[nt][1] = sm[SM_WHI + n * PITCH + w0 + 4];
                blo[nt][0] = sm[SM_WLO + n * PITCH + w0];
                blo[nt][1] = sm[SM_WLO + n * PITCH + w0 + 4];
            }
#pragma unroll
            for (int mt = 0; mt < 2; mt++)
#pragma unroll
                for (int nt = 0; nt < 4; nt++) {
                    mma_f16(acc[mt][nt], a[mt], blo[nt]);
                    mma_f16(acc[mt][nt], a[mt], bhi[nt]);
                }
        }

        __syncthreads();     // all warps done reading this buffer
        prefetch(t + 2 * g, aoff);  // refill it for the tile after next

        // epilogue (overlaps with the cp.async refill in flight)
        int m0 = t << 6;
#pragma unroll
        for (int mt = 0; mt < 2; mt++) {
            int r0 = m0 + warpM * 32 + mt * 16 + (lane >> 2);
#pragma unroll
            for (int nt = 0; nt < 4; nt++) {
                int col = warpN * 32 + nt * 8 + (lane & 3) * 2;
                if (r0 < N) {
                    float2 v = make_float2(acc[mt][nt][0] + bv[nt][0],
                                           acc[mt][nt][1] + bv[nt][1]);
                    *reinterpret_cast<float2*>(out + (size_t)r0 * OUTD + col) = v;
                }
                if (r0 + 8 < N) {
                    float2 v = make_float2(acc[mt][nt][2] + bv[nt][0],
                                           acc[mt][nt][3] + bv[nt][1]);
                    *reinterpret_cast<float2*>(out + (size_t)(r0 + 8) * OUTD + col) = v;
                }
            }
        }
    }
}

// ---------------------------------------------------------------------------
// Launch: 4 kernels. alpha+prep -> fill -> pull -> gemm.
// ---------------------------------------------------------------------------
extern "C" void kernel_launch(void* const* d_in, const int* in_sizes, int n_in,
                              void* d_out, int out_size) {
    const float* x      = (const float*)d_in[0];
    const float* x0     = (const float*)d_in[1];
    const float* ew     = (const float*)d_in[2];
    const float* att_l  = (const float*)d_in[3];
    const float* att_r  = (const float*)d_in[4];
    const float* W      = (const float*)d_in[5];
    const float* bias   = (const float*)d_in[6];
    const void*  ei     = (const void*)d_in[7];
    float* out = (float*)d_out;

    int N = in_sizes[1] / D;
    int E = in_sizes[2];

    static bool attr_set = false;
    if (!attr_set) {
        cudaFuncSetAttribute(gemm_kernel,
                             cudaFuncAttributeMaxDynamicSharedMemorySize,
                             SM_WORDS * 4);
        attr_set = true;
    }

    int ablocks = (N + 7) / 8;
    int nzero = (N + 255) / 256;
    alpha_prep_kernel<<<ablocks + 32 + nzero + 1, 256>>>(
        x, att_l, att_r, W, (const unsigned int*)ei, N, E, ablocks, nzero);

    fill_kernel<<<(E + 255) / 256, 256>>>(ei, ew, E);

    {
        int blocks = (N + 7) / 8;
        pull_kernel<<<blocks, 256>>>(x0, N);
    }

    gemm_kernel<<<296, 256, SM_WORDS * 4>>>(bias, out, N);
}